// round 8
// baseline (speedup 1.0000x reference)
#include <cuda_runtime.h>
#include <cuda_bf16.h>

// ---------------- problem constants (1,3,224,224) ----------------
#define HH    224
#define WW    224
#define NPIX  (HH * WW)
#define WSR   10
#define KK    21            // 2*WSR+1

#define EPSF  1e-6f
#define EPS08 1.5848931924611134e-05f     // (1e-6)^0.8
#define C_LW  (-72.134752044448169f)      // -SIG_COLOR * log2(e) = -50*1.4426950408889634
#define SIG_SPACE_F (1.0f / 98.0f)        // 1/(7*7*2)
#define C1F   10.0f
#define C2F   5.0f

// ---------------- tiling ----------------
#define TX    32
#define TY    4
#define NTHR  (TX * TY)          // 128
#define RR    (TY + WSR)         // 14 halo rows (forward offsets only: dy in [0,10])
#define CC    (TX + 2 * WSR)     // 52 halo cols
#define GXB   (WW / TX)          // 7
#define GYB   (HH / TY)          // 56
#define NBLK  (GXB * GYB)        // 392

// ---------------- scratch (device globals: no allocation) ----------------
__device__ float g_mask[NPIX];     // +1 = use_large, -1 = small branch
__device__ float g_part[NBLK];     // per-block partial sums

// MUFU wrappers (exp2/log2 approx — __exp2f does not exist as an intrinsic)
__device__ __forceinline__ float ex2f(float x) {
    float y; asm("ex2.approx.f32 %0, %1;" : "=f"(y) : "f"(x)); return y;
}
__device__ __forceinline__ float lg2f(float x) {
    float y; asm("lg2.approx.f32 %0, %1;" : "=f"(y) : "f"(x)); return y;
}

// wr * t^0.8 fused: exp2(0.8*log2(t) + lw), lw = C_LW * cd
__device__ __forceinline__ float powterm(float t, float lw) {
    return ex2f(fmaf(0.8f, lg2f(t), lw));
}

// ============================================================================
// Pass 1: per-pixel branch mask from edge responses, with early exit.
//   er(img)_i = sum over window & channels of |img_j - img_i| where img_j > 0.
//   use_large = (er_o < C1) && (er_s - er_o > C2).
// Since terms are non-negative, partial er_o >= C1 already decides the mask,
// which for random data happens within ~1 window row.
// ============================================================================
__global__ __launch_bounds__(256) void mask_kernel(
    const float* __restrict__ orig, const float* __restrict__ smv)
{
    int p = blockIdx.x * blockDim.x + threadIdx.x;
    if (p >= NPIX) return;
    int y = p / WW, x = p - y * WW;

    float oc0 = orig[p], oc1 = orig[NPIX + p], oc2 = orig[2 * NPIX + p];

    int xlo = max(x - WSR, 0), xhi = min(x + WSR, WW - 1);
    int ylo = max(y - WSR, 0), yhi = min(y + WSR, HH - 1);

    // --- er_o with early exit ---
    float ero = 0.0f;
    bool alive = true;
    for (int yy = ylo; yy <= yhi && alive; ++yy) {
        int rowb = yy * WW;
        for (int xx = xlo; xx <= xhi; ++xx) {
            int q = rowb + xx;
            float o0 = orig[q], o1 = orig[NPIX + q], o2 = orig[2 * NPIX + q];
            ero += (o0 > 0.0f) ? fabsf(o0 - oc0) : 0.0f;
            ero += (o1 > 0.0f) ? fabsf(o1 - oc1) : 0.0f;
            ero += (o2 > 0.0f) ? fabsf(o2 - oc2) : 0.0f;
        }
        if (ero >= C1F) alive = false;   // final er_o >= partial >= C1 -> use_large=false
    }

    bool useL = false;
    if (ero < C1F) {
        float sc0 = smv[p], sc1 = smv[NPIX + p], sc2 = smv[2 * NPIX + p];
        float ers = 0.0f;
        for (int yy = ylo; yy <= yhi; ++yy) {
            int rowb = yy * WW;
            for (int xx = xlo; xx <= xhi; ++xx) {
                int q = rowb + xx;
                float s0 = smv[q], s1 = smv[NPIX + q], s2 = smv[2 * NPIX + q];
                ers += (s0 > 0.0f) ? fabsf(s0 - sc0) : 0.0f;
                ers += (s1 > 0.0f) ? fabsf(s1 - sc1) : 0.0f;
                ers += (s2 > 0.0f) ? fabsf(s2 - sc2) : 0.0f;
            }
        }
        useL = (ers - ero) > C2F;
    }
    g_mask[p] = useL ? 1.0f : -1.0f;
}

// ============================================================================
// Pass 2: symmetric pair loop. Each pixel iterates the 220 forward offsets
// (dy==0: dx 1..10; dy 1..10: dx -10..10); each in-bounds unordered pair is
// computed once and credited to both endpoints via the mask weights.
// OOB neighbors (sentinel v==0 in padded mask plane) are skipped in the loop
// and accounted for analytically:  n_oob * wS_i * 3*eps^0.8 * exp(-50*|o_i|^2).
// Self term (k=center): wS_i * 3*eps^0.8.
// ============================================================================
template <bool LARGE>
__device__ __forceinline__ float window_sum(
    const float* __restrict__ ssp, const float* __restrict__ osp,
    const float* __restrict__ vsp, const float* __restrict__ ws1d,
    int tyy, int lx, int gx, int gy)
{
    const int base = tyy * CC + lx;
    const float si0 = ssp[base], si1 = ssp[RR * CC + base], si2 = ssp[2 * RR * CC + base];
    const float oi0 = osp[base], oi1 = osp[RR * CC + base], oi2 = osp[2 * RR * CC + base];
    const float vi  = vsp[base];
    const float wLi = fmaxf(vi, 0.0f), wSi = fmaxf(-vi, 0.0f);
    const float si_min = fminf(si0, fminf(si1, si2));

    // self term + analytic OOB terms
    int ninx = min(gx, WSR) + min(WW - 1 - gx, WSR) + 1;
    int niny = min(gy, WSR) + min(HH - 1 - gy, WSR) + 1;
    float noob = (float)(KK * KK - ninx * niny);
    float cdo  = fmaf(oi0, oi0, fmaf(oi1, oi1, oi2 * oi2));
    float acc  = wSi * (3.0f * EPS08) * fmaf(noob, ex2f(C_LW * cdo), 1.0f);

    auto pair = [&](int off, float ayw, float wx) {
        float sj0 = ssp[off], sj1 = ssp[RR * CC + off], sj2 = ssp[2 * RR * CC + off];
        float oj0 = osp[off], oj1 = osp[RR * CC + off], oj2 = osp[2 * RR * CC + off];
        float vj  = vsp[off];
        float d0 = oj0 - oi0, d1 = oj1 - oi1, d2 = oj2 - oi2;
        float lw = fmaf(d0, d0, fmaf(d1, d1, d2 * d2)) * C_LW;   // log2(wr)
        float e0 = sj0 - si0, e1 = sj1 - si1, e2 = sj2 - si2;
        float mn = fminf(sj0, fminf(sj1, sj2));
        if (mn > 0.0f && si_min > 0.0f) {
            // fast path: all channel masks pass on both sides
            float p = powterm(fabsf(e0) + EPSF, lw)
                    + powterm(fabsf(e1) + EPSF, lw)
                    + powterm(fabsf(e2) + EPSF, lw);
            float wSj = fmaxf(-vj, 0.0f);
            acc = fmaf(wSi + wSj, p, acc);
            if (LARGE) {
                float Q = fmaf(e0, e0, fmaf(e1, e1, e2 * e2));
                float wLj = fmaxf(vj, 0.0f);
                acc = fmaf(ayw * wx * (wLi + wLj), Q, acc);
            }
        } else if (vj != 0.0f) {
            // rare: an exact-zero sample value -> per-side channel masks differ
            float a0 = fabsf(e0), a1 = fabsf(e1), a2 = fabsf(e2);
            float tA0 = (sj0 > 0.0f) ? a0 : 0.0f;   // i's view: mask on s_j>0
            float tA1 = (sj1 > 0.0f) ? a1 : 0.0f;
            float tA2 = (sj2 > 0.0f) ? a2 : 0.0f;
            float tB0 = (si0 > 0.0f) ? a0 : 0.0f;   // j's view: mask on s_i>0
            float tB1 = (si1 > 0.0f) ? a1 : 0.0f;
            float tB2 = (si2 > 0.0f) ? a2 : 0.0f;
            float pA = powterm(tA0 + EPSF, lw) + powterm(tA1 + EPSF, lw) + powterm(tA2 + EPSF, lw);
            float pB = powterm(tB0 + EPSF, lw) + powterm(tB1 + EPSF, lw) + powterm(tB2 + EPSF, lw);
            float wSj = fmaxf(-vj, 0.0f);
            acc = fmaf(wSi, pA, fmaf(wSj, pB, acc));
            float QA = fmaf(tA0, tA0, fmaf(tA1, tA1, tA2 * tA2));
            float QB = fmaf(tB0, tB0, fmaf(tB1, tB1, tB2 * tB2));
            float wLj = fmaxf(vj, 0.0f);
            acc = fmaf(ayw * wx, fmaf(wLi, QA, wLj * QB), acc);
        }
        // vj == 0: OOB neighbor, covered by the analytic term above
    };

    // dy == 0, dx in [1, WSR]
    {
        float ayw = 5.0f * ws1d[WSR];
        #pragma unroll
        for (int dx = 1; dx <= WSR; ++dx)
            pair(base + dx, ayw, ws1d[WSR + dx]);
    }
    #pragma unroll 1
    for (int dy = 1; dy <= WSR; ++dy) {
        float ayw = 5.0f * ws1d[WSR + dy];
        int rb = base + dy * CC;
        #pragma unroll 3
        for (int dx = -WSR; dx <= WSR; ++dx)
            pair(rb + dx, ayw, ws1d[WSR + dx]);
    }
    return acc;
}

__global__ __launch_bounds__(NTHR) void loss_kernel(
    const float* __restrict__ orig, const float* __restrict__ smv)
{
    __shared__ float ssm[3 * RR * CC];
    __shared__ float som[3 * RR * CC];
    __shared__ float svm[RR * CC];
    __shared__ float ws1d[KK];
    __shared__ int   s_hasL;
    __shared__ float red[NTHR];

    const int tid = threadIdx.y * TX + threadIdx.x;
    if (tid == 0) s_hasL = 0;
    if (tid < KK) {
        int d = tid - WSR;
        ws1d[tid] = ex2f(-SIG_SPACE_F * 1.4426950408889634f * (float)(d * d));
    }

    const int x0 = blockIdx.x * TX, y0 = blockIdx.y * TY;

    int lflag = 0;
    for (int idx = tid; idx < RR * CC; idx += NTHR) {
        int r = idx / CC, i = idx - r * CC;
        int gy = y0 + r, gx = x0 - WSR + i;
        float s0 = 0, s1 = 0, s2 = 0, o0 = 0, o1 = 0, o2 = 0, v = 0;
        if (gy < HH && (unsigned)gx < (unsigned)WW) {
            int gi = gy * WW + gx;
            s0 = smv[gi]; s1 = smv[NPIX + gi]; s2 = smv[2 * NPIX + gi];
            o0 = orig[gi]; o1 = orig[NPIX + gi]; o2 = orig[2 * NPIX + gi];
            v  = g_mask[gi];
        }
        ssm[idx] = s0; ssm[RR * CC + idx] = s1; ssm[2 * RR * CC + idx] = s2;
        som[idx] = o0; som[RR * CC + idx] = o1; som[2 * RR * CC + idx] = o2;
        svm[idx] = v;
        lflag |= (v > 0.0f) ? 1 : 0;
    }
    __syncthreads();
    if (lflag) s_hasL = 1;
    __syncthreads();

    const int gx = x0 + threadIdx.x, gy = y0 + threadIdx.y;
    float acc;
    if (s_hasL) acc = window_sum<true >(ssm, som, svm, ws1d, threadIdx.y, threadIdx.x + WSR, gx, gy);
    else        acc = window_sum<false>(ssm, som, svm, ws1d, threadIdx.y, threadIdx.x + WSR, gx, gy);

    red[tid] = acc;
    __syncthreads();
    #pragma unroll
    for (int s = NTHR / 2; s > 0; s >>= 1) {
        if (tid < s) red[tid] += red[tid + s];
        __syncthreads();
    }
    if (tid == 0) g_part[blockIdx.y * gridDim.x + blockIdx.x] = red[0];
}

// ============================================================================
// Pass 3: deterministic final reduction (fp64) + scaling.
// ============================================================================
__global__ __launch_bounds__(256) void reduce_kernel(float* __restrict__ out)
{
    __shared__ double rd[256];
    double s = 0.0;
    for (int i = threadIdx.x; i < NBLK; i += 256) s += (double)g_part[i];
    rd[threadIdx.x] = s;
    __syncthreads();
    #pragma unroll
    for (int k = 128; k > 0; k >>= 1) {
        if (threadIdx.x < k) rd[threadIdx.x] += rd[threadIdx.x + k];
        __syncthreads();
    }
    if (threadIdx.x == 0) {
        const double scale = 1.0 / ((double)HH * (double)WW) / (double)(WSR * WSR);
        out[0] = (float)(rd[0] * scale);
    }
}

extern "C" void kernel_launch(void* const* d_in, const int* in_sizes, int n_in,
                              void* d_out, int out_size)
{
    (void)in_sizes; (void)n_in; (void)out_size;
    const float* orig = (const float*)d_in[0];   // original_images (1,3,224,224)
    const float* smv  = (const float*)d_in[1];   // smooth_images   (1,3,224,224)
    float* out = (float*)d_out;

    mask_kernel<<<(NPIX + 255) / 256, 256>>>(orig, smv);

    dim3 grid(GXB, GYB);
    dim3 blk(TX, TY);
    loss_kernel<<<grid, blk>>>(orig, smv);

    reduce_kernel<<<1, 256>>>(out);
}